// round 12
// baseline (speedup 1.0000x reference)
#include <cuda_runtime.h>
#include <cuda_bf16.h>
#include <math_constants.h>

// RationalQuadraticSpline: B=65536, V=64, K=30 bins.
//   K1 (64 blocks): build packed tables + 256-cell u16 LUT.
//   K2: smem tables; DUAL-STREAM float4 eval (i and i+n4/2 per iter) for 2x
//       independent memory/FP chains per thread (latency-bound regime).
// Guaranteed bin width >= 1e-3 + 0.97/(30e) = 0.0129, so each 1/256 cell holds
// at most one knot -> u16 LUT packs bin(5b) + quantized knot threshold(11b).

#define V_VARS 64
#define KBINS  30
#define LUTN   256

__device__ __align__(16) float4         g_Q0[V_VARS * 32];  // icw, invw, ich, ih
__device__ __align__(16) float4         g_Q1[V_VARS * 32];  // idl, d0, cc, idl2
__device__ __align__(16) unsigned short g_lut[V_VARS * LUTN];

// ---------------------------------------------------------------------------
// Build kernel: one block per variable, 128 threads. Warp 0 computes params.
// ---------------------------------------------------------------------------
__global__ __launch_bounds__(128, 8)
void rqs_build_kernel(const float* __restrict__ uw,
                      const float* __restrict__ uh,
                      const float* __restrict__ ud)
{
    __shared__ float s_kn[32];   // kn[0..30], kn[30] = 1 + 1e-6

    const int v    = blockIdx.x;
    const int tid  = threadIdx.x;
    const int lane = tid & 31;
    const unsigned FULL = 0xffffffffu;

    if (tid < 32) {
        // ---------- widths: softmax + floor + scan ----------
        float u = (lane < KBINS) ? uw[v * KBINS + lane] : -CUDART_INF_F;
        float m = u;
        #pragma unroll
        for (int o = 16; o > 0; o >>= 1) m = fmaxf(m, __shfl_xor_sync(FULL, m, o));
        float e = (lane < KBINS) ? expf(u - m) : 0.0f;
        float s = e;
        #pragma unroll
        for (int o = 16; o > 0; o >>= 1) s += __shfl_xor_sync(FULL, s, o);
        float size = 1e-3f + (1.0f - 30.0f * 1e-3f) * (e / s);
        if (lane >= KBINS) size = 0.0f;
        float csw = size;
        #pragma unroll
        for (int o = 1; o < 32; o <<= 1) {
            float t = __shfl_up_sync(FULL, csw, o);
            if (lane >= o) csw += t;
        }
        float cplo = __shfl_up_sync(FULL, csw, 1);
        if (lane == 0) cplo = 0.0f;
        float cphi = (lane == KBINS - 1) ? 1.0f : csw;
        float invw = 1.0f / (cphi - cplo);

        // ---------- heights ----------
        float uhh = (lane < KBINS) ? uh[v * KBINS + lane] : -CUDART_INF_F;
        float mh = uhh;
        #pragma unroll
        for (int o = 16; o > 0; o >>= 1) mh = fmaxf(mh, __shfl_xor_sync(FULL, mh, o));
        float eh = (lane < KBINS) ? expf(uhh - mh) : 0.0f;
        float sh = eh;
        #pragma unroll
        for (int o = 16; o > 0; o >>= 1) sh += __shfl_xor_sync(FULL, sh, o);
        float sizeh = 1e-3f + (1.0f - 30.0f * 1e-3f) * (eh / sh);
        if (lane >= KBINS) sizeh = 0.0f;
        float csh = sizeh;
        #pragma unroll
        for (int o = 1; o < 32; o <<= 1) {
            float t = __shfl_up_sync(FULL, csh, o);
            if (lane >= o) csh += t;
        }
        float cploh = __shfl_up_sync(FULL, csh, 1);
        if (lane == 0) cploh = 0.0f;
        float cphih = (lane == KBINS - 1) ? 1.0f : csh;
        float hgt = cphih - cploh;

        // ---------- derivatives: lane k holds d[k], k=0..30 ----------
        const float SPC = logf(expf(1.0f - 1e-3f) - 1.0f);  // pins boundary to 1
        float udv = (lane == 0 || lane >= KBINS) ? SPC : ud[v * (KBINS - 1) + lane - 1];
        float sp  = (udv > 20.0f) ? udv : log1pf(expf(udv));
        float d0  = 1e-3f + sp;
        float d1  = __shfl_down_sync(FULL, d0, 1);

        // ---------- stores ----------
        float idl  = hgt * invw;
        float cc   = (d0 + d1) - 2.0f * idl;
        float idl2 = idl * idl;
        if (lane < KBINS) {
            g_Q0[v * 32 + lane] = make_float4(cplo, invw, cploh, hgt);
            g_Q1[v * 32 + lane] = make_float4(idl, d0, cc, idl2);
        } else {
            g_Q0[v * 32 + lane] = make_float4(0.f, 1.f, 0.f, 0.f);
            g_Q1[v * 32 + lane] = make_float4(1.f, 1.f, 0.f, 1.f);
        }
        float kn;
        if (lane < KBINS)       kn = cplo;
        else if (lane == KBINS) kn = 1.0f + 1e-6f;
        else                    kn = 2.0f;
        s_kn[lane] = kn;
    }
    __syncthreads();

    // ---------- LUT: cell -> (bin, quantized next-knot threshold) ----------
    for (int c = tid; c < LUTN; c += blockDim.x) {
        float c0 = (float)c * (1.0f / (float)LUTN);
        int b = 0;
        #pragma unroll
        for (int k = 1; k < KBINS; k++) b += (c0 >= s_kn[k]);
        float r = (s_kn[b + 1] - c0) * (float)LUTN;   // knot pos within cell, >0
        int kq = (int)(r * 2048.0f);
        if (kq > 2047) kq = 2047;                     // 2047 == sentinel (no knot)
        g_lut[v * LUTN + c] = (unsigned short)((kq << 5) | b);
    }
}

// ---------------------------------------------------------------------------
// Main kernel
// ---------------------------------------------------------------------------
__device__ __forceinline__ void rqs_eval(
    float x,
    const float4* __restrict__ Q0v,
    const float4* __restrict__ Q1v,
    const unsigned short* __restrict__ Lv,
    float& o, float& l)
{
    float xc = __saturatef(x);
    float xs = xc * (float)LUTN;
    int cell = min((int)xs, LUTN - 1);
    unsigned e = Lv[cell];
    int b = (int)(e & 31u);
    float t = (e >= 0xFFE0u) ? 2.0f : (float)(e >> 5) * (1.0f / 2048.0f);
    float x_rel = xs - (float)cell;
    b += (x_rel >= t);

    float4 q0 = Q0v[b];         // icw, invw, ich, ih
    float4 q1 = Q1v[b];         // idl, d0, cc, idl2

    float th   = (xc - q0.x) * q0.y;
    float th2  = th * th;
    float t1mt = th - th2;
    float h    = q1.x - q1.y;                      // idl - d0

    float np   = fmaf(h, th, q1.y);                // d0 + (idl-d0)*th
    float den  = fmaf(q1.z, t1mt, q1.x);
    float rden = __fdividef(1.0f, den);
    float oi   = fmaf((q0.w * th) * np, rden, q0.z);
    float poly = fmaf(fmaf(q1.z, th, h + h), th, q1.y);
    float li   = __logf(q1.w * poly * (rden * rden));

    bool inside = (x == xc);
    o = inside ? oi : x;        // DERIV_OUT == 1 -> linear tails are identity
    l = inside ? li : 0.0f;
}

__global__ __launch_bounds__(1024)
void RationalQuadraticSpline_40973988004342_kernel(
    const float* __restrict__ inp,
    float* __restrict__ out,
    int n)
{
    extern __shared__ unsigned char smem[];
    float4*         s_Q0 = (float4*)smem;                       // 32 KB
    float4*         s_Q1 = (float4*)(smem + 32768);             // 32 KB
    unsigned short* s_L  = (unsigned short*)(smem + 65536);     // 32 KB

    const int tid = threadIdx.x;

    // table copy from global (int4 granularity)
    {
        const int4* s0 = (const int4*)g_Q0;
        int4* d0 = (int4*)s_Q0;
        for (int i = tid; i < V_VARS * 32; i += blockDim.x) d0[i] = s0[i];
        const int4* s1 = (const int4*)g_Q1;
        int4* d1 = (int4*)s_Q1;
        for (int i = tid; i < V_VARS * 32; i += blockDim.x) d1[i] = s1[i];
        const int4* sl = (const int4*)g_lut;
        int4* dl = (int4*)s_L;
        for (int i = tid; i < (V_VARS * LUTN * 2) / 16; i += blockDim.x) dl[i] = sl[i];
    }
    __syncthreads();

    int g = blockIdx.x * blockDim.x + tid;
    // v of element 4*g is constant across grid-stride iters (stride % 16 == 0),
    // and 4*(n4/2) % 64 == 0 so stream B shares the same tables.
    int vA = (g << 2) & (V_VARS - 1);
    const float4* q00 = s_Q0 + (vA + 0) * 32;
    const float4* q01 = s_Q0 + (vA + 1) * 32;
    const float4* q02 = s_Q0 + (vA + 2) * 32;
    const float4* q03 = s_Q0 + (vA + 3) * 32;
    const float4* q10 = s_Q1 + (vA + 0) * 32;
    const float4* q11 = s_Q1 + (vA + 1) * 32;
    const float4* q12 = s_Q1 + (vA + 2) * 32;
    const float4* q13 = s_Q1 + (vA + 3) * 32;
    const unsigned short* l0 = s_L + (vA + 0) * LUTN;
    const unsigned short* l1 = s_L + (vA + 1) * LUTN;
    const unsigned short* l2 = s_L + (vA + 2) * LUTN;
    const unsigned short* l3 = s_L + (vA + 3) * LUTN;

    const float4* __restrict__ in4 = (const float4*)inp;
    float4* __restrict__ out4 = (float4*)out;
    float4* __restrict__ lad4 = (float4*)(out + n);
    int n4 = n >> 2;
    int half = n4 >> 1;
    int stride = gridDim.x * blockDim.x;

    for (int i = g; i < half; i += stride) {
        float4 xa = in4[i];
        float4 xb = in4[i + half];
        float4 oa, la, ob, lb;
        rqs_eval(xa.x, q00, q10, l0, oa.x, la.x);
        rqs_eval(xb.x, q00, q10, l0, ob.x, lb.x);
        rqs_eval(xa.y, q01, q11, l1, oa.y, la.y);
        rqs_eval(xb.y, q01, q11, l1, ob.y, lb.y);
        rqs_eval(xa.z, q02, q12, l2, oa.z, la.z);
        rqs_eval(xb.z, q02, q12, l2, ob.z, lb.z);
        rqs_eval(xa.w, q03, q13, l3, oa.w, la.w);
        rqs_eval(xb.w, q03, q13, l3, ob.w, lb.w);
        out4[i] = oa;
        lad4[i] = la;
        out4[i + half] = ob;
        lad4[i + half] = lb;
    }

    // defensive tails (n4 odd middle float4, and n % 4 != 0) — block 0 only
    if (blockIdx.x == 0) {
        for (int i = 2 * half + tid; i < n4; i += blockDim.x) {
            float4 xv = in4[i];
            int v = (i << 2) & (V_VARS - 1);
            float4 ov, lv;
            rqs_eval(xv.x, s_Q0 + (v + 0) * 32, s_Q1 + (v + 0) * 32, s_L + (v + 0) * LUTN, ov.x, lv.x);
            rqs_eval(xv.y, s_Q0 + (v + 1) * 32, s_Q1 + (v + 1) * 32, s_L + (v + 1) * LUTN, ov.y, lv.y);
            rqs_eval(xv.z, s_Q0 + (v + 2) * 32, s_Q1 + (v + 2) * 32, s_L + (v + 2) * LUTN, ov.z, lv.z);
            rqs_eval(xv.w, s_Q0 + (v + 3) * 32, s_Q1 + (v + 3) * 32, s_L + (v + 3) * LUTN, ov.w, lv.w);
            out4[i] = ov;
            lad4[i] = lv;
        }
        for (int e = (n & ~3) + tid; e < n; e += blockDim.x) {
            int v = e & (V_VARS - 1);
            float o, l;
            rqs_eval(inp[e], s_Q0 + v * 32, s_Q1 + v * 32, s_L + v * LUTN, o, l);
            out[e] = o;
            out[n + e] = l;
        }
    }
}

extern "C" void kernel_launch(void* const* d_in, const int* in_sizes, int n_in,
                              void* d_out, int out_size)
{
    const float* inp = (const float*)d_in[0];
    const float* uw  = (const float*)d_in[1];
    const float* uh  = (const float*)d_in[2];
    const float* ud  = (const float*)d_in[3];
    float* out = (float*)d_out;
    int n = in_sizes[0];

    const int MAIN_SMEM = 32768 * 3;  // 96 KB
    static int configured = 0;
    if (!configured) {
        cudaFuncSetAttribute(RationalQuadraticSpline_40973988004342_kernel,
                             cudaFuncAttributeMaxDynamicSharedMemorySize, MAIN_SMEM);
        configured = 1;
    }

    rqs_build_kernel<<<V_VARS, 128>>>(uw, uh, ud);

    int n4 = n >> 2;
    int half = n4 >> 1;
    int blocks = 304;
    int maxb = (half + 1023) / 1024;
    if (maxb < 1) maxb = 1;
    if (blocks > maxb) blocks = maxb;

    RationalQuadraticSpline_40973988004342_kernel<<<blocks, 1024, MAIN_SMEM>>>(inp, out, n);
}

// round 13
// speedup vs baseline: 1.0012x; 1.0012x over previous
#include <cuda_runtime.h>
#include <cuda_bf16.h>
#include <math_constants.h>

// RationalQuadraticSpline: B=65536, V=64, K=30 bins.
//   K1 (64 blocks): build packed tables + 256-cell u16 LUT.
//   K2: smem tables; DUAL-STREAM float4 eval (i and i+n4/2 per iter) for 2x
//       independent memory/FP chains per thread (latency-bound regime).
// Guaranteed bin width >= 1e-3 + 0.97/(30e) = 0.0129, so each 1/256 cell holds
// at most one knot -> u16 LUT packs bin(5b) + quantized knot threshold(11b).

#define V_VARS 64
#define KBINS  30
#define LUTN   256

__device__ __align__(16) float4         g_Q0[V_VARS * 32];  // icw, invw, ich, ih
__device__ __align__(16) float4         g_Q1[V_VARS * 32];  // idl, d0, cc, idl2
__device__ __align__(16) unsigned short g_lut[V_VARS * LUTN];

// ---------------------------------------------------------------------------
// Build kernel: one block per variable, 128 threads. Warp 0 computes params.
// ---------------------------------------------------------------------------
__global__ __launch_bounds__(128, 8)
void rqs_build_kernel(const float* __restrict__ uw,
                      const float* __restrict__ uh,
                      const float* __restrict__ ud)
{
    __shared__ float s_kn[32];   // kn[0..30], kn[30] = 1 + 1e-6

    const int v    = blockIdx.x;
    const int tid  = threadIdx.x;
    const int lane = tid & 31;
    const unsigned FULL = 0xffffffffu;

    if (tid < 32) {
        // ---------- widths: softmax + floor + scan ----------
        float u = (lane < KBINS) ? uw[v * KBINS + lane] : -CUDART_INF_F;
        float m = u;
        #pragma unroll
        for (int o = 16; o > 0; o >>= 1) m = fmaxf(m, __shfl_xor_sync(FULL, m, o));
        float e = (lane < KBINS) ? expf(u - m) : 0.0f;
        float s = e;
        #pragma unroll
        for (int o = 16; o > 0; o >>= 1) s += __shfl_xor_sync(FULL, s, o);
        float size = 1e-3f + (1.0f - 30.0f * 1e-3f) * (e / s);
        if (lane >= KBINS) size = 0.0f;
        float csw = size;
        #pragma unroll
        for (int o = 1; o < 32; o <<= 1) {
            float t = __shfl_up_sync(FULL, csw, o);
            if (lane >= o) csw += t;
        }
        float cplo = __shfl_up_sync(FULL, csw, 1);
        if (lane == 0) cplo = 0.0f;
        float cphi = (lane == KBINS - 1) ? 1.0f : csw;
        float invw = 1.0f / (cphi - cplo);

        // ---------- heights ----------
        float uhh = (lane < KBINS) ? uh[v * KBINS + lane] : -CUDART_INF_F;
        float mh = uhh;
        #pragma unroll
        for (int o = 16; o > 0; o >>= 1) mh = fmaxf(mh, __shfl_xor_sync(FULL, mh, o));
        float eh = (lane < KBINS) ? expf(uhh - mh) : 0.0f;
        float sh = eh;
        #pragma unroll
        for (int o = 16; o > 0; o >>= 1) sh += __shfl_xor_sync(FULL, sh, o);
        float sizeh = 1e-3f + (1.0f - 30.0f * 1e-3f) * (eh / sh);
        if (lane >= KBINS) sizeh = 0.0f;
        float csh = sizeh;
        #pragma unroll
        for (int o = 1; o < 32; o <<= 1) {
            float t = __shfl_up_sync(FULL, csh, o);
            if (lane >= o) csh += t;
        }
        float cploh = __shfl_up_sync(FULL, csh, 1);
        if (lane == 0) cploh = 0.0f;
        float cphih = (lane == KBINS - 1) ? 1.0f : csh;
        float hgt = cphih - cploh;

        // ---------- derivatives: lane k holds d[k], k=0..30 ----------
        const float SPC = logf(expf(1.0f - 1e-3f) - 1.0f);  // pins boundary to 1
        float udv = (lane == 0 || lane >= KBINS) ? SPC : ud[v * (KBINS - 1) + lane - 1];
        float sp  = (udv > 20.0f) ? udv : log1pf(expf(udv));
        float d0  = 1e-3f + sp;
        float d1  = __shfl_down_sync(FULL, d0, 1);

        // ---------- stores ----------
        float idl  = hgt * invw;
        float cc   = (d0 + d1) - 2.0f * idl;
        float idl2 = idl * idl;
        if (lane < KBINS) {
            g_Q0[v * 32 + lane] = make_float4(cplo, invw, cploh, hgt);
            g_Q1[v * 32 + lane] = make_float4(idl, d0, cc, idl2);
        } else {
            g_Q0[v * 32 + lane] = make_float4(0.f, 1.f, 0.f, 0.f);
            g_Q1[v * 32 + lane] = make_float4(1.f, 1.f, 0.f, 1.f);
        }
        float kn;
        if (lane < KBINS)       kn = cplo;
        else if (lane == KBINS) kn = 1.0f + 1e-6f;
        else                    kn = 2.0f;
        s_kn[lane] = kn;
    }
    __syncthreads();

    // ---------- LUT: cell -> (bin, quantized next-knot threshold) ----------
    for (int c = tid; c < LUTN; c += blockDim.x) {
        float c0 = (float)c * (1.0f / (float)LUTN);
        int b = 0;
        #pragma unroll
        for (int k = 1; k < KBINS; k++) b += (c0 >= s_kn[k]);
        float r = (s_kn[b + 1] - c0) * (float)LUTN;   // knot pos within cell, >0
        int kq = (int)(r * 2048.0f);
        if (kq > 2047) kq = 2047;                     // 2047 == sentinel (no knot)
        g_lut[v * LUTN + c] = (unsigned short)((kq << 5) | b);
    }
}

// ---------------------------------------------------------------------------
// Main kernel
// ---------------------------------------------------------------------------
__device__ __forceinline__ void rqs_eval(
    float x,
    const float4* __restrict__ Q0v,
    const float4* __restrict__ Q1v,
    const unsigned short* __restrict__ Lv,
    float& o, float& l)
{
    float xc = __saturatef(x);
    float xs = xc * (float)LUTN;
    int cell = min((int)xs, LUTN - 1);
    unsigned e = Lv[cell];
    int b = (int)(e & 31u);
    float t = (e >= 0xFFE0u) ? 2.0f : (float)(e >> 5) * (1.0f / 2048.0f);
    float x_rel = xs - (float)cell;
    b += (x_rel >= t);

    float4 q0 = Q0v[b];         // icw, invw, ich, ih
    float4 q1 = Q1v[b];         // idl, d0, cc, idl2

    float th   = (xc - q0.x) * q0.y;
    float th2  = th * th;
    float t1mt = th - th2;
    float h    = q1.x - q1.y;                      // idl - d0

    float np   = fmaf(h, th, q1.y);                // d0 + (idl-d0)*th
    float den  = fmaf(q1.z, t1mt, q1.x);
    float rden = __fdividef(1.0f, den);
    float oi   = fmaf((q0.w * th) * np, rden, q0.z);
    float poly = fmaf(fmaf(q1.z, th, h + h), th, q1.y);
    float li   = __logf(q1.w * poly * (rden * rden));

    bool inside = (x == xc);
    o = inside ? oi : x;        // DERIV_OUT == 1 -> linear tails are identity
    l = inside ? li : 0.0f;
}

__global__ __launch_bounds__(1024)
void RationalQuadraticSpline_40973988004342_kernel(
    const float* __restrict__ inp,
    float* __restrict__ out,
    int n)
{
    extern __shared__ unsigned char smem[];
    float4*         s_Q0 = (float4*)smem;                       // 32 KB
    float4*         s_Q1 = (float4*)(smem + 32768);             // 32 KB
    unsigned short* s_L  = (unsigned short*)(smem + 65536);     // 32 KB

    const int tid = threadIdx.x;

    // table copy from global (int4 granularity)
    {
        const int4* s0 = (const int4*)g_Q0;
        int4* d0 = (int4*)s_Q0;
        for (int i = tid; i < V_VARS * 32; i += blockDim.x) d0[i] = s0[i];
        const int4* s1 = (const int4*)g_Q1;
        int4* d1 = (int4*)s_Q1;
        for (int i = tid; i < V_VARS * 32; i += blockDim.x) d1[i] = s1[i];
        const int4* sl = (const int4*)g_lut;
        int4* dl = (int4*)s_L;
        for (int i = tid; i < (V_VARS * LUTN * 2) / 16; i += blockDim.x) dl[i] = sl[i];
    }
    __syncthreads();

    int g = blockIdx.x * blockDim.x + tid;
    // v of element 4*g is constant across grid-stride iters (stride % 16 == 0),
    // and 4*(n4/2) % 64 == 0 so stream B shares the same tables.
    int vA = (g << 2) & (V_VARS - 1);
    const float4* q00 = s_Q0 + (vA + 0) * 32;
    const float4* q01 = s_Q0 + (vA + 1) * 32;
    const float4* q02 = s_Q0 + (vA + 2) * 32;
    const float4* q03 = s_Q0 + (vA + 3) * 32;
    const float4* q10 = s_Q1 + (vA + 0) * 32;
    const float4* q11 = s_Q1 + (vA + 1) * 32;
    const float4* q12 = s_Q1 + (vA + 2) * 32;
    const float4* q13 = s_Q1 + (vA + 3) * 32;
    const unsigned short* l0 = s_L + (vA + 0) * LUTN;
    const unsigned short* l1 = s_L + (vA + 1) * LUTN;
    const unsigned short* l2 = s_L + (vA + 2) * LUTN;
    const unsigned short* l3 = s_L + (vA + 3) * LUTN;

    const float4* __restrict__ in4 = (const float4*)inp;
    float4* __restrict__ out4 = (float4*)out;
    float4* __restrict__ lad4 = (float4*)(out + n);
    int n4 = n >> 2;
    int half = n4 >> 1;
    int stride = gridDim.x * blockDim.x;

    for (int i = g; i < half; i += stride) {
        float4 xa = in4[i];
        float4 xb = in4[i + half];
        float4 oa, la, ob, lb;
        rqs_eval(xa.x, q00, q10, l0, oa.x, la.x);
        rqs_eval(xb.x, q00, q10, l0, ob.x, lb.x);
        rqs_eval(xa.y, q01, q11, l1, oa.y, la.y);
        rqs_eval(xb.y, q01, q11, l1, ob.y, lb.y);
        rqs_eval(xa.z, q02, q12, l2, oa.z, la.z);
        rqs_eval(xb.z, q02, q12, l2, ob.z, lb.z);
        rqs_eval(xa.w, q03, q13, l3, oa.w, la.w);
        rqs_eval(xb.w, q03, q13, l3, ob.w, lb.w);
        out4[i] = oa;
        lad4[i] = la;
        out4[i + half] = ob;
        lad4[i + half] = lb;
    }

    // defensive tails (n4 odd middle float4, and n % 4 != 0) — block 0 only
    if (blockIdx.x == 0) {
        for (int i = 2 * half + tid; i < n4; i += blockDim.x) {
            float4 xv = in4[i];
            int v = (i << 2) & (V_VARS - 1);
            float4 ov, lv;
            rqs_eval(xv.x, s_Q0 + (v + 0) * 32, s_Q1 + (v + 0) * 32, s_L + (v + 0) * LUTN, ov.x, lv.x);
            rqs_eval(xv.y, s_Q0 + (v + 1) * 32, s_Q1 + (v + 1) * 32, s_L + (v + 1) * LUTN, ov.y, lv.y);
            rqs_eval(xv.z, s_Q0 + (v + 2) * 32, s_Q1 + (v + 2) * 32, s_L + (v + 2) * LUTN, ov.z, lv.z);
            rqs_eval(xv.w, s_Q0 + (v + 3) * 32, s_Q1 + (v + 3) * 32, s_L + (v + 3) * LUTN, ov.w, lv.w);
            out4[i] = ov;
            lad4[i] = lv;
        }
        for (int e = (n & ~3) + tid; e < n; e += blockDim.x) {
            int v = e & (V_VARS - 1);
            float o, l;
            rqs_eval(inp[e], s_Q0 + v * 32, s_Q1 + v * 32, s_L + v * LUTN, o, l);
            out[e] = o;
            out[n + e] = l;
        }
    }
}

extern "C" void kernel_launch(void* const* d_in, const int* in_sizes, int n_in,
                              void* d_out, int out_size)
{
    const float* inp = (const float*)d_in[0];
    const float* uw  = (const float*)d_in[1];
    const float* uh  = (const float*)d_in[2];
    const float* ud  = (const float*)d_in[3];
    float* out = (float*)d_out;
    int n = in_sizes[0];

    const int MAIN_SMEM = 32768 * 3;  // 96 KB
    static int configured = 0;
    if (!configured) {
        cudaFuncSetAttribute(RationalQuadraticSpline_40973988004342_kernel,
                             cudaFuncAttributeMaxDynamicSharedMemorySize, MAIN_SMEM);
        configured = 1;
    }

    rqs_build_kernel<<<V_VARS, 128>>>(uw, uh, ud);

    int n4 = n >> 2;
    int half = n4 >> 1;
    int blocks = 304;
    int maxb = (half + 1023) / 1024;
    if (maxb < 1) maxb = 1;
    if (blocks > maxb) blocks = maxb;

    RationalQuadraticSpline_40973988004342_kernel<<<blocks, 1024, MAIN_SMEM>>>(inp, out, n);
}

// round 14
// speedup vs baseline: 1.0156x; 1.0144x over previous
#include <cuda_runtime.h>
#include <cuda_bf16.h>
#include <math_constants.h>

// RationalQuadraticSpline: B=65536, V=64, K=30 bins.
//   K1 (64 blocks): build packed tables + 256-cell u16 LUT.
//   K2: smem tables; DUAL-STREAM float4 eval (i and i+n4/2 per iter) for 2x
//       independent memory/FP chains per thread (latency-bound regime).
// Guaranteed bin width >= 1e-3 + 0.97/(30e) = 0.0129, so each 1/256 cell holds
// at most one knot -> u16 LUT packs bin(5b) + quantized knot threshold(11b).

#define V_VARS 64
#define KBINS  30
#define LUTN   256

__device__ __align__(16) float4         g_Q0[V_VARS * 32];  // icw, invw, ich, ih
__device__ __align__(16) float4         g_Q1[V_VARS * 32];  // idl, d0, cc, idl2
__device__ __align__(16) unsigned short g_lut[V_VARS * LUTN];

// ---------------------------------------------------------------------------
// Build kernel: one block per variable, 128 threads. Warp 0 computes params.
// ---------------------------------------------------------------------------
__global__ __launch_bounds__(128, 8)
void rqs_build_kernel(const float* __restrict__ uw,
                      const float* __restrict__ uh,
                      const float* __restrict__ ud)
{
    __shared__ float s_kn[32];   // kn[0..30], kn[30] = 1 + 1e-6

    const int v    = blockIdx.x;
    const int tid  = threadIdx.x;
    const int lane = tid & 31;
    const unsigned FULL = 0xffffffffu;

    if (tid < 32) {
        // ---------- widths: softmax + floor + scan ----------
        float u = (lane < KBINS) ? uw[v * KBINS + lane] : -CUDART_INF_F;
        float m = u;
        #pragma unroll
        for (int o = 16; o > 0; o >>= 1) m = fmaxf(m, __shfl_xor_sync(FULL, m, o));
        float e = (lane < KBINS) ? expf(u - m) : 0.0f;
        float s = e;
        #pragma unroll
        for (int o = 16; o > 0; o >>= 1) s += __shfl_xor_sync(FULL, s, o);
        float size = 1e-3f + (1.0f - 30.0f * 1e-3f) * (e / s);
        if (lane >= KBINS) size = 0.0f;
        float csw = size;
        #pragma unroll
        for (int o = 1; o < 32; o <<= 1) {
            float t = __shfl_up_sync(FULL, csw, o);
            if (lane >= o) csw += t;
        }
        float cplo = __shfl_up_sync(FULL, csw, 1);
        if (lane == 0) cplo = 0.0f;
        float cphi = (lane == KBINS - 1) ? 1.0f : csw;
        float invw = 1.0f / (cphi - cplo);

        // ---------- heights ----------
        float uhh = (lane < KBINS) ? uh[v * KBINS + lane] : -CUDART_INF_F;
        float mh = uhh;
        #pragma unroll
        for (int o = 16; o > 0; o >>= 1) mh = fmaxf(mh, __shfl_xor_sync(FULL, mh, o));
        float eh = (lane < KBINS) ? expf(uhh - mh) : 0.0f;
        float sh = eh;
        #pragma unroll
        for (int o = 16; o > 0; o >>= 1) sh += __shfl_xor_sync(FULL, sh, o);
        float sizeh = 1e-3f + (1.0f - 30.0f * 1e-3f) * (eh / sh);
        if (lane >= KBINS) sizeh = 0.0f;
        float csh = sizeh;
        #pragma unroll
        for (int o = 1; o < 32; o <<= 1) {
            float t = __shfl_up_sync(FULL, csh, o);
            if (lane >= o) csh += t;
        }
        float cploh = __shfl_up_sync(FULL, csh, 1);
        if (lane == 0) cploh = 0.0f;
        float cphih = (lane == KBINS - 1) ? 1.0f : csh;
        float hgt = cphih - cploh;

        // ---------- derivatives: lane k holds d[k], k=0..30 ----------
        const float SPC = logf(expf(1.0f - 1e-3f) - 1.0f);  // pins boundary to 1
        float udv = (lane == 0 || lane >= KBINS) ? SPC : ud[v * (KBINS - 1) + lane - 1];
        float sp  = (udv > 20.0f) ? udv : log1pf(expf(udv));
        float d0  = 1e-3f + sp;
        float d1  = __shfl_down_sync(FULL, d0, 1);

        // ---------- stores ----------
        float idl  = hgt * invw;
        float cc   = (d0 + d1) - 2.0f * idl;
        float idl2 = idl * idl;
        if (lane < KBINS) {
            g_Q0[v * 32 + lane] = make_float4(cplo, invw, cploh, hgt);
            g_Q1[v * 32 + lane] = make_float4(idl, d0, cc, idl2);
        } else {
            g_Q0[v * 32 + lane] = make_float4(0.f, 1.f, 0.f, 0.f);
            g_Q1[v * 32 + lane] = make_float4(1.f, 1.f, 0.f, 1.f);
        }
        float kn;
        if (lane < KBINS)       kn = cplo;
        else if (lane == KBINS) kn = 1.0f + 1e-6f;
        else                    kn = 2.0f;
        s_kn[lane] = kn;
    }
    __syncthreads();

    // ---------- LUT: cell -> (bin, quantized next-knot threshold) ----------
    for (int c = tid; c < LUTN; c += blockDim.x) {
        float c0 = (float)c * (1.0f / (float)LUTN);
        int b = 0;
        #pragma unroll
        for (int k = 1; k < KBINS; k++) b += (c0 >= s_kn[k]);
        float r = (s_kn[b + 1] - c0) * (float)LUTN;   // knot pos within cell, >0
        int kq = (int)(r * 2048.0f);
        if (kq > 2047) kq = 2047;                     // 2047 == sentinel (no knot)
        g_lut[v * LUTN + c] = (unsigned short)((kq << 5) | b);
    }
}

// ---------------------------------------------------------------------------
// Main kernel
// ---------------------------------------------------------------------------
__device__ __forceinline__ void rqs_eval(
    float x,
    const float4* __restrict__ Q0v,
    const float4* __restrict__ Q1v,
    const unsigned short* __restrict__ Lv,
    float& o, float& l)
{
    float xc = __saturatef(x);
    float xs = xc * (float)LUTN;
    int cell = min((int)xs, LUTN - 1);
    unsigned e = Lv[cell];
    int b = (int)(e & 31u);
    float t = (e >= 0xFFE0u) ? 2.0f : (float)(e >> 5) * (1.0f / 2048.0f);
    float x_rel = xs - (float)cell;
    b += (x_rel >= t);

    float4 q0 = Q0v[b];         // icw, invw, ich, ih
    float4 q1 = Q1v[b];         // idl, d0, cc, idl2

    float th   = (xc - q0.x) * q0.y;
    float th2  = th * th;
    float t1mt = th - th2;
    float h    = q1.x - q1.y;                      // idl - d0

    float np   = fmaf(h, th, q1.y);                // d0 + (idl-d0)*th
    float den  = fmaf(q1.z, t1mt, q1.x);
    float rden = __fdividef(1.0f, den);
    float oi   = fmaf((q0.w * th) * np, rden, q0.z);
    float poly = fmaf(fmaf(q1.z, th, h + h), th, q1.y);
    float li   = __logf(q1.w * poly * (rden * rden));

    bool inside = (x == xc);
    o = inside ? oi : x;        // DERIV_OUT == 1 -> linear tails are identity
    l = inside ? li : 0.0f;
}

__global__ __launch_bounds__(1024)
void RationalQuadraticSpline_40973988004342_kernel(
    const float* __restrict__ inp,
    float* __restrict__ out,
    int n)
{
    extern __shared__ unsigned char smem[];
    float4*         s_Q0 = (float4*)smem;                       // 32 KB
    float4*         s_Q1 = (float4*)(smem + 32768);             // 32 KB
    unsigned short* s_L  = (unsigned short*)(smem + 65536);     // 32 KB

    const int tid = threadIdx.x;

    // table copy from global (int4 granularity)
    {
        const int4* s0 = (const int4*)g_Q0;
        int4* d0 = (int4*)s_Q0;
        for (int i = tid; i < V_VARS * 32; i += blockDim.x) d0[i] = s0[i];
        const int4* s1 = (const int4*)g_Q1;
        int4* d1 = (int4*)s_Q1;
        for (int i = tid; i < V_VARS * 32; i += blockDim.x) d1[i] = s1[i];
        const int4* sl = (const int4*)g_lut;
        int4* dl = (int4*)s_L;
        for (int i = tid; i < (V_VARS * LUTN * 2) / 16; i += blockDim.x) dl[i] = sl[i];
    }
    __syncthreads();

    int g = blockIdx.x * blockDim.x + tid;
    // v of element 4*g is constant across grid-stride iters (stride % 16 == 0),
    // and 4*(n4/2) % 64 == 0 so stream B shares the same tables.
    int vA = (g << 2) & (V_VARS - 1);
    const float4* q00 = s_Q0 + (vA + 0) * 32;
    const float4* q01 = s_Q0 + (vA + 1) * 32;
    const float4* q02 = s_Q0 + (vA + 2) * 32;
    const float4* q03 = s_Q0 + (vA + 3) * 32;
    const float4* q10 = s_Q1 + (vA + 0) * 32;
    const float4* q11 = s_Q1 + (vA + 1) * 32;
    const float4* q12 = s_Q1 + (vA + 2) * 32;
    const float4* q13 = s_Q1 + (vA + 3) * 32;
    const unsigned short* l0 = s_L + (vA + 0) * LUTN;
    const unsigned short* l1 = s_L + (vA + 1) * LUTN;
    const unsigned short* l2 = s_L + (vA + 2) * LUTN;
    const unsigned short* l3 = s_L + (vA + 3) * LUTN;

    const float4* __restrict__ in4 = (const float4*)inp;
    float4* __restrict__ out4 = (float4*)out;
    float4* __restrict__ lad4 = (float4*)(out + n);
    int n4 = n >> 2;
    int half = n4 >> 1;
    int stride = gridDim.x * blockDim.x;

    for (int i = g; i < half; i += stride) {
        float4 xa = in4[i];
        float4 xb = in4[i + half];
        float4 oa, la, ob, lb;
        rqs_eval(xa.x, q00, q10, l0, oa.x, la.x);
        rqs_eval(xb.x, q00, q10, l0, ob.x, lb.x);
        rqs_eval(xa.y, q01, q11, l1, oa.y, la.y);
        rqs_eval(xb.y, q01, q11, l1, ob.y, lb.y);
        rqs_eval(xa.z, q02, q12, l2, oa.z, la.z);
        rqs_eval(xb.z, q02, q12, l2, ob.z, lb.z);
        rqs_eval(xa.w, q03, q13, l3, oa.w, la.w);
        rqs_eval(xb.w, q03, q13, l3, ob.w, lb.w);
        out4[i] = oa;
        lad4[i] = la;
        out4[i + half] = ob;
        lad4[i + half] = lb;
    }

    // defensive tails (n4 odd middle float4, and n % 4 != 0) — block 0 only
    if (blockIdx.x == 0) {
        for (int i = 2 * half + tid; i < n4; i += blockDim.x) {
            float4 xv = in4[i];
            int v = (i << 2) & (V_VARS - 1);
            float4 ov, lv;
            rqs_eval(xv.x, s_Q0 + (v + 0) * 32, s_Q1 + (v + 0) * 32, s_L + (v + 0) * LUTN, ov.x, lv.x);
            rqs_eval(xv.y, s_Q0 + (v + 1) * 32, s_Q1 + (v + 1) * 32, s_L + (v + 1) * LUTN, ov.y, lv.y);
            rqs_eval(xv.z, s_Q0 + (v + 2) * 32, s_Q1 + (v + 2) * 32, s_L + (v + 2) * LUTN, ov.z, lv.z);
            rqs_eval(xv.w, s_Q0 + (v + 3) * 32, s_Q1 + (v + 3) * 32, s_L + (v + 3) * LUTN, ov.w, lv.w);
            out4[i] = ov;
            lad4[i] = lv;
        }
        for (int e = (n & ~3) + tid; e < n; e += blockDim.x) {
            int v = e & (V_VARS - 1);
            float o, l;
            rqs_eval(inp[e], s_Q0 + v * 32, s_Q1 + v * 32, s_L + v * LUTN, o, l);
            out[e] = o;
            out[n + e] = l;
        }
    }
}

extern "C" void kernel_launch(void* const* d_in, const int* in_sizes, int n_in,
                              void* d_out, int out_size)
{
    const float* inp = (const float*)d_in[0];
    const float* uw  = (const float*)d_in[1];
    const float* uh  = (const float*)d_in[2];
    const float* ud  = (const float*)d_in[3];
    float* out = (float*)d_out;
    int n = in_sizes[0];

    const int MAIN_SMEM = 32768 * 3;  // 96 KB
    static int configured = 0;
    if (!configured) {
        cudaFuncSetAttribute(RationalQuadraticSpline_40973988004342_kernel,
                             cudaFuncAttributeMaxDynamicSharedMemorySize, MAIN_SMEM);
        configured = 1;
    }

    rqs_build_kernel<<<V_VARS, 128>>>(uw, uh, ud);

    int n4 = n >> 2;
    int half = n4 >> 1;
    int blocks = 304;
    int maxb = (half + 1023) / 1024;
    if (maxb < 1) maxb = 1;
    if (blocks > maxb) blocks = maxb;

    RationalQuadraticSpline_40973988004342_kernel<<<blocks, 1024, MAIN_SMEM>>>(inp, out, n);
}